// round 9
// baseline (speedup 1.0000x reference)
#include <cuda_runtime.h>
#include <cuda_bf16.h>
#include <cstdint>

#define Bn 64
#define Qn 2048
#define Kn 2048
#define Dn 128

// ---------------- scratch (device globals; no allocation) ----------------
__device__ __align__(256) __nv_bfloat16 g_qh[(size_t)Bn * Qn * Dn];
__device__ __align__(256) __nv_bfloat16 g_ql[(size_t)Bn * Qn * Dn];
__device__ __align__(256) __nv_bfloat16 g_kh[(size_t)Bn * Kn * Dn];
__device__ __align__(256) __nv_bfloat16 g_kl[(size_t)Bn * Kn * Dn];
__device__ __align__(256) __nv_bfloat16 g_vth[(size_t)Bn * Dn * Kn];  // [b][d][k]
__device__ __align__(256) __nv_bfloat16 g_vtl[(size_t)Bn * Dn * Kn];
__device__ __align__(256) __nv_bfloat16 g_eh[(size_t)Bn * Qn * Kn];   // E hi
__device__ __align__(256) __nv_bfloat16 g_el[(size_t)Bn * Qn * Kn];   // E lo
__device__ __align__(256) float g_ps[(size_t)Bn * Qn * 64];   // partial sums per 32-col block
__device__ __align__(256) float g_is[(size_t)Bn * Qn];        // 1/row sum

// ---------------- helpers ----------------
#define MMA_BF16(C, a0, a1, a2, a3, b0, b1)                                   \
  asm volatile(                                                               \
      "mma.sync.aligned.m16n8k16.row.col.f32.bf16.bf16.f32 "                  \
      "{%0,%1,%2,%3}, {%4,%5,%6,%7}, {%8,%9}, {%0,%1,%2,%3};\n"               \
      : "+f"(C[0]), "+f"(C[1]), "+f"(C[2]), "+f"(C[3])                        \
      : "r"(a0), "r"(a1), "r"(a2), "r"(a3), "r"(b0), "r"(b1))

__device__ __forceinline__ void splitpack(float x, float y, uint32_t& h, uint32_t& l) {
    __nv_bfloat162 hh = __floats2bfloat162_rn(x, y);
    float hx = __low2float(hh);
    float hy = __high2float(hh);
    __nv_bfloat162 ll = __floats2bfloat162_rn(x - hx, y - hy);
    h = *reinterpret_cast<uint32_t*>(&hh);
    l = *reinterpret_cast<uint32_t*>(&ll);
}
__device__ __forceinline__ uint32_t smem_u32(const void* p) {
    return (uint32_t)__cvta_generic_to_shared(p);
}
__device__ __forceinline__ void cpasync16(uint32_t dst, const void* src) {
    asm volatile("cp.async.cg.shared.global [%0], [%1], 16;\n" :: "r"(dst), "l"(src));
}
#define CP_COMMIT asm volatile("cp.async.commit_group;\n" ::: "memory")
#define CP_WAIT0  asm volatile("cp.async.wait_group 0;\n" ::: "memory")
#define CP_WAIT1  asm volatile("cp.async.wait_group 1;\n" ::: "memory")

// ================= K0a: fp32 -> (hi, lo) bf16 =================
__global__ void __launch_bounds__(256)
convert_kernel(const float* __restrict__ x, __nv_bfloat16* __restrict__ h,
               __nv_bfloat16* __restrict__ l)
{
    int i = blockIdx.x * 256 + threadIdx.x;
    float4 v = ((const float4*)x)[i];
    uint32_t h0, l0, h1, l1;
    splitpack(v.x, v.y, h0, l0);
    splitpack(v.z, v.w, h1, l1);
    ((uint2*)h)[i] = make_uint2(h0, h1);
    ((uint2*)l)[i] = make_uint2(l0, l1);
}

// ================= K0b: V fp32 [b][k][d] -> bf16 hi/lo [b][d][k] =================
__global__ void __launch_bounds__(256)
transpose_conv_kernel(const float* __restrict__ v,
                      __nv_bfloat16* __restrict__ th, __nv_bfloat16* __restrict__ tl)
{
    __shared__ float t[32][33];
    const int b  = blockIdx.z;
    const int k0 = blockIdx.x * 32;
    const int d0 = blockIdx.y * 32;
    const int tx = threadIdx.x & 31;
    const int ty = threadIdx.x >> 5;
#pragma unroll
    for (int i = 0; i < 4; i++) {
        int k = ty + i * 8;
        t[k][tx] = v[((size_t)b * Kn + k0 + k) * Dn + d0 + tx];
    }
    __syncthreads();
#pragma unroll
    for (int i = 0; i < 4; i++) {
        int d = ty + i * 8;
        float x = t[tx][d];
        __nv_bfloat16 hb = __float2bfloat16_rn(x);
        __nv_bfloat16 lb = __float2bfloat16_rn(x - __bfloat162float(hb));
        size_t o = ((size_t)b * Dn + d0 + d) * Kn + k0 + tx;
        th[o] = hb;
        tl[o] = lb;
    }
}

// ================= K1: persistent scores -> E(hi/lo bf16) + partial sums =================
// Grid (Qn/128, Bn). 512 threads. Q tile resident; K tiles (N=128) double-buffered.
#define K1S 136                 /* bf16 row stride (272 bytes) */
#define SC_OFF_QH 0
#define SC_OFF_QL 34816
#define SC_OFF_K0 69632         /* buf0: Kh at +0, Kl at +34816 */
#define SC_OFF_K1 139264        /* buf1 */
#define SC_SMEM   208896
#define SC_SCALE 0.08838834764831845f

__global__ void __launch_bounds__(512, 1)
scores_kernel(const __nv_bfloat16* __restrict__ qh, const __nv_bfloat16* __restrict__ ql,
              const __nv_bfloat16* __restrict__ kh, const __nv_bfloat16* __restrict__ kl,
              const int* __restrict__ vlg,
              __nv_bfloat16* __restrict__ ehg, __nv_bfloat16* __restrict__ elg,
              float* __restrict__ ps)
{
    extern __shared__ unsigned char sm[];
    const uint32_t base = smem_u32(sm);
    const uint32_t uQh = base + SC_OFF_QH;
    const uint32_t uQl = base + SC_OFF_QL;
    __nv_bfloat16* sQh = (__nv_bfloat16*)(sm + SC_OFF_QH);
    __nv_bfloat16* sQl = (__nv_bfloat16*)(sm + SC_OFF_QL);

    const int b  = blockIdx.y;
    const int i0 = blockIdx.x * 128;
    const int tid = threadIdx.x;
    const int w = tid >> 5, lane = tid & 31;
    const int g = lane >> 2, ct = lane & 3;
    const int wm = w >> 2, wn = w & 3;          // 4x4 warp grid: 32 rows x 32 cols each
    const int m0 = wm * 32, n0v = wn * 32;
    const int VL = vlg[b];
    const float mval = (VL == 0) ? 1.0f : 0.0f;

    const __nv_bfloat16* bq_h = qh + ((size_t)b * Qn + i0) * Dn;
    const __nv_bfloat16* bq_l = ql + ((size_t)b * Qn + i0) * Dn;
    const __nv_bfloat16* bk_h = kh + (size_t)b * Kn * Dn;
    const __nv_bfloat16* bk_l = kl + (size_t)b * Kn * Dn;

    // ---- Q load (commit group) ----
#pragma unroll
    for (int rep = 0; rep < 4; rep++) {
        int idx = tid + rep * 512;          // 0..2047 = 128 rows x 16 chunks
        int r = idx >> 4, c8 = idx & 15;
        uint32_t dsto = r * (K1S * 2) + c8 * 16;
        size_t srco = (size_t)r * Dn + c8 * 8;
        cpasync16(uQh + dsto, bq_h + srco);
        cpasync16(uQl + dsto, bq_l + srco);
    }
    CP_COMMIT;

    // ---- K tile loader ----
    auto load_k = [&](int j, int buf) {
        uint32_t ukh = base + (buf ? SC_OFF_K1 : SC_OFF_K0);
        uint32_t ukl = ukh + 34816;
#pragma unroll
        for (int rep = 0; rep < 4; rep++) {
            int idx = tid + rep * 512;
            int r = idx >> 4, c8 = idx & 15;
            uint32_t dsto = r * (K1S * 2) + c8 * 16;
            size_t srco = (size_t)(j * 128 + r) * Dn + c8 * 8;
            cpasync16(ukh + dsto, bk_h + srco);
            cpasync16(ukl + dsto, bk_l + srco);
        }
        CP_COMMIT;
    };
    load_k(0, 0);

    for (int j = 0; j < 16; j++) {
        if (j < 15) {
            load_k(j + 1, (j + 1) & 1);
            CP_WAIT1;              // Q + K(j) complete; K(j+1) may be in flight
        } else {
            CP_WAIT0;
        }
        __syncthreads();

        const __nv_bfloat16* sKh = (__nv_bfloat16*)(sm + ((j & 1) ? SC_OFF_K1 : SC_OFF_K0));
        const __nv_bfloat16* sKl = sKh + 17408;   // +34816 bytes

        float acc[2][4][4] = {};
#pragma unroll
        for (int kk = 0; kk < 8; kk++) {
            uint32_t ah[2][4], al[2][4];
#pragma unroll
            for (int mf = 0; mf < 2; mf++) {
                const __nv_bfloat16* p0 = sQh + (m0 + mf * 16 + g) * K1S + kk * 16 + 2 * ct;
                ah[mf][0] = *(const uint32_t*)p0;
                ah[mf][1] = *(const uint32_t*)(p0 + 8 * K1S);
                ah[mf][2] = *(const uint32_t*)(p0 + 8);
                ah[mf][3] = *(const uint32_t*)(p0 + 8 * K1S + 8);
                const __nv_bfloat16* p1 = sQl + (m0 + mf * 16 + g) * K1S + kk * 16 + 2 * ct;
                al[mf][0] = *(const uint32_t*)p1;
                al[mf][1] = *(const uint32_t*)(p1 + 8 * K1S);
                al[mf][2] = *(const uint32_t*)(p1 + 8);
                al[mf][3] = *(const uint32_t*)(p1 + 8 * K1S + 8);
            }
#pragma unroll
            for (int nf = 0; nf < 4; nf++) {
                const __nv_bfloat16* kb = sKh + (n0v + nf * 8 + g) * K1S + kk * 16 + 2 * ct;
                uint32_t bh0 = *(const uint32_t*)kb;
                uint32_t bh1 = *(const uint32_t*)(kb + 8);
                const __nv_bfloat16* kc = sKl + (n0v + nf * 8 + g) * K1S + kk * 16 + 2 * ct;
                uint32_t bl0 = *(const uint32_t*)kc;
                uint32_t bl1 = *(const uint32_t*)(kc + 8);
#pragma unroll
                for (int mf = 0; mf < 2; mf++) {
                    MMA_BF16(acc[mf][nf], ah[mf][0], ah[mf][1], ah[mf][2], ah[mf][3], bh0, bh1);
                    MMA_BF16(acc[mf][nf], ah[mf][0], ah[mf][1], ah[mf][2], ah[mf][3], bl0, bl1);
                    MMA_BF16(acc[mf][nf], al[mf][0], al[mf][1], al[mf][2], al[mf][3], bh0, bh1);
                }
            }
        }
        __syncthreads();   // all warps done reading this K buffer

        // ---- epilogue: scale, mask, exp, bf16-split store, partial sums ----
        const int jbase = j * 128;
#pragma unroll
        for (int mf = 0; mf < 2; mf++) {
#pragma unroll
            for (int h = 0; h < 2; h++) {
                const int row = m0 + mf * 16 + h * 8 + g;
                float se = 0.f;
#pragma unroll
                for (int nf = 0; nf < 4; nf++) {
                    int col = jbase + n0v + nf * 8 + 2 * ct;
                    float e0 = (col     < VL) ? __expf(acc[mf][nf][2 * h]     * SC_SCALE) : mval;
                    float e1 = (col + 1 < VL) ? __expf(acc[mf][nf][2 * h + 1] * SC_SCALE) : mval;
                    uint32_t hb, lb;
                    splitpack(e0, e1, hb, lb);
                    size_t o = ((size_t)b * Qn + i0 + row) * Kn + col;
                    *(uint32_t*)(ehg + o) = hb;
                    *(uint32_t*)(elg + o) = lb;
                    se += e0 + e1;
                }
                se += __shfl_xor_sync(0xffffffffu, se, 1);
                se += __shfl_xor_sync(0xffffffffu, se, 2);
                if (ct == 0)
                    ps[((size_t)b * Qn + i0 + row) * 64 + j * 4 + wn] = se;
            }
        }
    }
}

// ================= K1b: reduce partials -> 1/row sum =================
__global__ void __launch_bounds__(256)
reduce_kernel(const float* __restrict__ ps, float* __restrict__ iso)
{
    int i = blockIdx.x * 256 + threadIdx.x;
    const float4* s4 = (const float4*)(ps + (size_t)i * 64);
    float sum = 0.f;
#pragma unroll
    for (int t = 0; t < 16; t++) {
        float4 sv = s4[t];
        sum += (sv.x + sv.y) + (sv.z + sv.w);
    }
    iso[i] = 1.0f / sum;
}

// ================= K2: attn writeback + PV GEMM (pure bf16 inner loop) =================
#define PS2 72    /* bf16 stride, E tiles (k-contiguous) */
#define VS 72     /* bf16 stride, Vt tiles               */
#define K2_OFF_EH 0
#define K2_OFF_EL 18432
#define K2_OFF_VH 36864
#define K2_OFF_VL 55296
#define K2_OFF_IV 73728
#define K2_SMEM   (K2_OFF_IV + 128 * 4)    /* 74240 */

__global__ void __launch_bounds__(256, 2)
pv_kernel(const __nv_bfloat16* __restrict__ ehg, const __nv_bfloat16* __restrict__ elg,
          const __nv_bfloat16* __restrict__ vth, const __nv_bfloat16* __restrict__ vtl,
          const float* __restrict__ isg,
          float* __restrict__ att, float* __restrict__ outg)
{
    extern __shared__ unsigned char sm[];
    __nv_bfloat16* sEh = (__nv_bfloat16*)(sm + K2_OFF_EH);
    __nv_bfloat16* sEl = (__nv_bfloat16*)(sm + K2_OFF_EL);
    __nv_bfloat16* sVh = (__nv_bfloat16*)(sm + K2_OFF_VH);
    __nv_bfloat16* sVl = (__nv_bfloat16*)(sm + K2_OFF_VL);
    float*         sIv = (float*)(sm + K2_OFF_IV);

    const int b  = blockIdx.y;
    const int i0 = blockIdx.x * 128;
    const int tid = threadIdx.x;
    const int w = tid >> 5, lane = tid & 31;
    const int g = lane >> 2, ct = lane & 3;
    const int wm = w >> 1, wn = w & 1;

    const __nv_bfloat16* eh_g = ehg + ((size_t)b * Qn + i0) * Kn;
    const __nv_bfloat16* el_g = elg + ((size_t)b * Qn + i0) * Kn;
    const __nv_bfloat16* vh_g = vth + (size_t)b * Dn * Kn;
    const __nv_bfloat16* vl_g = vtl + (size_t)b * Dn * Kn;
    float* Ag = att + ((size_t)b * Qn + i0) * Kn;
    uint32_t uEh = smem_u32(sEh), uEl = smem_u32(sEl);
    uint32_t uVh = smem_u32(sVh), uVl = smem_u32(sVl);

    if (tid < 128) sIv[tid] = isg[(size_t)b * Qn + i0 + tid];

    float ris[2][2];
#pragma unroll
    for (int mf = 0; mf < 2; mf++)
#pragma unroll
        for (int h = 0; h < 2; h++)
            ris[mf][h] = isg[(size_t)b * Qn + i0 + wm * 32 + mf * 16 + h * 8 + g];

    float acc[2][8][4] = {};

    for (int c0 = 0; c0 < Kn; c0 += 64) {
        __syncthreads();
        // E tiles: 128 rows x 64 bf16 each (hi/lo)
#pragma unroll
        for (int rep = 0; rep < 4; rep++) {
            int idx = tid + rep * 256;      // 0..1023 = 128 rows x 8 chunks
            int r = idx >> 3, c8 = idx & 7;
            uint32_t dsto = r * (PS2 * 2) + c8 * 16;
            size_t srco = (size_t)r * Kn + c0 + c8 * 8;
            cpasync16(uEh + dsto, eh_g + srco);
            cpasync16(uEl + dsto, el_g + srco);
        }
        // Vt tiles: 128 d-rows x 64 bf16 each (hi/lo)
#pragma unroll
        for (int rep = 0; rep < 4; rep++) {
            int idx = tid + rep * 256;
            int d = idx >> 3, c8 = idx & 7;
            uint32_t dsto = d * (VS * 2) + c8 * 16;
            size_t srco = (size_t)d * Kn + c0 + c8 * 8;
            cpasync16(uVh + dsto, vh_g + srco);
            cpasync16(uVl + dsto, vl_g + srco);
        }
        CP_COMMIT; CP_WAIT0;
        __syncthreads();

        // attn writeback: attn = (eh + el) * inv, coalesced float4
#pragma unroll
        for (int rep = 0; rep < 8; rep++) {
            int idx = tid + rep * 256;      // 0..2047 = 128 rows x 16 quad-cols
            int r = idx >> 4, c4 = idx & 15;
            float iv = sIv[r];
            const __nv_bfloat162* hp = (const __nv_bfloat162*)(sEh + r * PS2 + c4 * 4);
            const __nv_bfloat162* lp = (const __nv_bfloat162*)(sEl + r * PS2 + c4 * 4);
            float2 h0 = __bfloat1622float2(hp[0]);
            float2 h1 = __bfloat1622float2(hp[1]);
            float2 l0 = __bfloat1622float2(lp[0]);
            float2 l1 = __bfloat1622float2(lp[1]);
            float4 o;
            o.x = (h0.x + l0.x) * iv;
            o.y = (h0.y + l0.y) * iv;
            o.z = (h1.x + l1.x) * iv;
            o.w = (h1.y + l1.y) * iv;
            *(float4*)(Ag + (size_t)r * Kn + c0 + c4 * 4) = o;
        }

#pragma unroll
        for (int kk = 0; kk < 4; kk++) {
            uint32_t ah[2][4], al[2][4];
#pragma unroll
            for (int mf = 0; mf < 2; mf++) {
                const __nv_bfloat16* p0 = sEh + (wm * 32 + mf * 16 + g) * PS2 + kk * 16 + 2 * ct;
                ah[mf][0] = *(const uint32_t*)p0;
                ah[mf][1] = *(const uint32_t*)(p0 + 8 * PS2);
                ah[mf][2] = *(const uint32_t*)(p0 + 8);
                ah[mf][3] = *(const uint32_t*)(p0 + 8 * PS2 + 8);
                const __nv_bfloat16* p1 = sEl + (wm * 32 + mf * 16 + g) * PS2 + kk * 16 + 2 * ct;
                al[mf][0] = *(const uint32_t*)p1;
                al[mf][1] = *(const uint32_t*)(p1 + 8 * PS2);
                al[mf][2] = *(const uint32_t*)(p1 + 8);
                al[mf][3] = *(const uint32_t*)(p1 + 8 * PS2 + 8);
            }
#pragma unroll
            for (int nf = 0; nf < 8; nf++) {
                const __nv_bfloat16* vb = sVh + (wn * 64 + nf * 8 + g) * VS + kk * 16 + 2 * ct;
                uint32_t bh0 = *(const uint32_t*)vb;
                uint32_t bh1 = *(const uint32_t*)(vb + 8);
                const __nv_bfloat16* vc = sVl + (wn * 64 + nf * 8 + g) * VS + kk * 16 + 2 * ct;
                uint32_t bl0 = *(const uint32_t*)vc;
                uint32_t bl1 = *(const uint32_t*)(vc + 8);
#pragma unroll
                for (int mf = 0; mf < 2; mf++) {
                    MMA_BF16(acc[mf][nf], ah[mf][0], ah[mf][1], ah[mf][2], ah[mf][3], bh0, bh1);
                    MMA_BF16(acc[mf][nf], ah[mf][0], ah[mf][1], ah[mf][2], ah[mf][3], bl0, bl1);
                    MMA_BF16(acc[mf][nf], al[mf][0], al[mf][1], al[mf][2], al[mf][3], bh0, bh1);
                }
            }
        }
    }

    float* op = outg + ((size_t)b * Qn + i0) * Dn;
#pragma unroll
    for (int mf = 0; mf < 2; mf++)
#pragma unroll
        for (int nf = 0; nf < 8; nf++) {
            int row = wm * 32 + mf * 16 + g;
            int col = wn * 64 + nf * 8 + 2 * ct;
            float i0v = ris[mf][0], i1v = ris[mf][1];
            *(float2*)(op + (size_t)row * Dn + col) =
                make_float2(acc[mf][nf][0] * i0v, acc[mf][nf][1] * i0v);
            *(float2*)(op + (size_t)(row + 8) * Dn + col) =
                make_float2(acc[mf][nf][2] * i1v, acc[mf][nf][3] * i1v);
        }
}

// ================= launch =================
extern "C" void kernel_launch(void* const* d_in, const int* in_sizes, int n_in,
                              void* d_out, int out_size) {
    const float* q  = (const float*)d_in[0];
    const float* k  = (const float*)d_in[1];
    const float* v  = (const float*)d_in[2];
    const int*   vl = (const int*)d_in[3];
    float* out  = (float*)d_out;
    float* attn = out + (size_t)Bn * Qn * Dn;   // output tuple: (out, attn)

    void *p_qh, *p_ql, *p_kh, *p_kl, *p_vth, *p_vtl, *p_eh, *p_el, *p_ps, *p_is;
    cudaGetSymbolAddress(&p_qh, g_qh);
    cudaGetSymbolAddress(&p_ql, g_ql);
    cudaGetSymbolAddress(&p_kh, g_kh);
    cudaGetSymbolAddress(&p_kl, g_kl);
    cudaGetSymbolAddress(&p_vth, g_vth);
    cudaGetSymbolAddress(&p_vtl, g_vtl);
    cudaGetSymbolAddress(&p_eh, g_eh);
    cudaGetSymbolAddress(&p_el, g_el);
    cudaGetSymbolAddress(&p_ps, g_ps);
    cudaGetSymbolAddress(&p_is, g_is);

    cudaFuncSetAttribute(scores_kernel, cudaFuncAttributeMaxDynamicSharedMemorySize, SC_SMEM);
    cudaFuncSetAttribute(pv_kernel,     cudaFuncAttributeMaxDynamicSharedMemorySize, K2_SMEM);

    const int n4 = Bn * Qn * Dn / 4;
    convert_kernel<<<n4 / 256, 256>>>(q, (__nv_bfloat16*)p_qh, (__nv_bfloat16*)p_ql);
    convert_kernel<<<n4 / 256, 256>>>(k, (__nv_bfloat16*)p_kh, (__nv_bfloat16*)p_kl);
    transpose_conv_kernel<<<dim3(Kn / 32, Dn / 32, Bn), 256>>>(v, (__nv_bfloat16*)p_vth,
                                                               (__nv_bfloat16*)p_vtl);

    scores_kernel<<<dim3(Qn / 128, Bn), 512, SC_SMEM>>>(
        (const __nv_bfloat16*)p_qh, (const __nv_bfloat16*)p_ql,
        (const __nv_bfloat16*)p_kh, (const __nv_bfloat16*)p_kl,
        vl, (__nv_bfloat16*)p_eh, (__nv_bfloat16*)p_el, (float*)p_ps);

    reduce_kernel<<<Bn * Qn / 256, 256>>>((const float*)p_ps, (float*)p_is);

    pv_kernel<<<dim3(Qn / 128, Bn), 256, K2_SMEM>>>(
        (const __nv_bfloat16*)p_eh, (const __nv_bfloat16*)p_el,
        (const __nv_bfloat16*)p_vth, (const __nv_bfloat16*)p_vtl,
        (const float*)p_is, attn, out);
}